// round 1
// baseline (speedup 1.0000x reference)
#include <cuda_runtime.h>
#include <math.h>

// Problem dims
#define Bn 32
#define Pn 256
#define Nn 1024
#define En 512
#define Hn 16
#define Dn 32

// Scratch (no allocations allowed)
__device__ float g_q[Bn*Hn*Pn*Dn];      // [B,H,P,D] q_first + q_last
__device__ float g_attn[Bn*Pn*En];      // [B,P,H*D] attention out (concat layout)
__device__ float g_mh[Bn*Pn*En];        // [B,P,E] combined heads
__device__ float g_rowsum[Bn*Pn];       // pointer-softmax denominators

// ---------------------------------------------------------------------------
// Kernel A: q = q_first + reshape(enc @ Wq^T)
// GEMM: [8192,512] x [512,512]^T, 64x64x16 tiles, 4x4 microtile
// ---------------------------------------------------------------------------
__global__ __launch_bounds__(256) void qlast_kernel(
    const float* __restrict__ enc, const float* __restrict__ Wq,
    const float* __restrict__ qf)
{
    const int mtile = blockIdx.y * 64, otile = blockIdx.x * 64;
    __shared__ float As[16][64];
    __shared__ float Ws[16][64];
    const int tid = threadIdx.x, tx = tid & 15, ty = tid >> 4;
    const int lr = tid >> 2, lk = (tid & 3) * 4;
    float acc[4][4] = {};

    for (int k0 = 0; k0 < 512; k0 += 16) {
        float4 a = *(const float4*)&enc[(mtile + lr) * 512 + k0 + lk];
        As[lk+0][lr] = a.x; As[lk+1][lr] = a.y; As[lk+2][lr] = a.z; As[lk+3][lr] = a.w;
        float4 w = *(const float4*)&Wq[(otile + lr) * 512 + k0 + lk];
        Ws[lk+0][lr] = w.x; Ws[lk+1][lr] = w.y; Ws[lk+2][lr] = w.z; Ws[lk+3][lr] = w.w;
        __syncthreads();
        #pragma unroll
        for (int kk = 0; kk < 16; kk++) {
            float4 av = *(const float4*)&As[kk][ty * 4];
            float4 bv = *(const float4*)&Ws[kk][tx * 4];
            float aa[4] = {av.x, av.y, av.z, av.w};
            float bb[4] = {bv.x, bv.y, bv.z, bv.w};
            #pragma unroll
            for (int i = 0; i < 4; i++)
                #pragma unroll
                for (int j = 0; j < 4; j++)
                    acc[i][j] += aa[i] * bb[j];
        }
        __syncthreads();
    }

    // Epilogue: scatter into [B,H,P,D] and add q_first
    const int o0 = otile + tx * 4;
    const int h = o0 >> 5, d0 = o0 & 31;   // 4 consecutive d stay within one head
    #pragma unroll
    for (int i = 0; i < 4; i++) {
        int m = mtile + ty * 4 + i;
        int b = m >> 8, p = m & 255;
        int idx = ((b * 16 + h) * 256 + p) * 32 + d0;
        float4 q4 = *(const float4*)&qf[idx];
        float4 o;
        o.x = acc[i][0] + q4.x; o.y = acc[i][1] + q4.y;
        o.z = acc[i][2] + q4.z; o.w = acc[i][3] + q4.w;
        *(float4*)&g_q[idx] = o;
    }
}

// ---------------------------------------------------------------------------
// Kernel B: fused masked MHA (flash-style, online softmax)
// grid: (B*H, P/64), block 256. Each thread: 1 row x 16-col group; acc[32].
// ---------------------------------------------------------------------------
__global__ __launch_bounds__(256, 2) void attn_kernel(
    const float* __restrict__ kmat, const float* __restrict__ vmat,
    const float* __restrict__ mask)
{
    const int bh = blockIdx.x;
    const int b = bh >> 4;
    const int p0 = blockIdx.y * 64;
    const int tid = threadIdx.x;
    const int row = tid >> 2, cg = tid & 3;
    const int p = p0 + row;

    __shared__ float ks[64 * 32];       // k chunk, [col][d] flat
    __shared__ float vt[32][65];        // v chunk transposed [d][col], padded

    // q row in registers (4 threads/row redundantly hold it; broadcast loads)
    float q[32];
    const float* qrow = &g_q[(bh * 256 + p) * 32];
    #pragma unroll
    for (int i = 0; i < 32; i += 4) {
        float4 t = *(const float4*)&qrow[i];
        q[i] = t.x; q[i+1] = t.y; q[i+2] = t.z; q[i+3] = t.w;
    }

    float acc[32];
    #pragma unroll
    for (int d = 0; d < 32; d++) acc[d] = 0.f;
    float mrun = -INFINITY, lrun = 0.f;

    const float* kbase = kmat + (size_t)bh * 1024 * 32;
    const float* vbase = vmat + (size_t)bh * 1024 * 32;
    const float* mrow  = mask + ((size_t)b * 256 + p) * 1024;
    const float inv_sqrt_d = 0.1767766952966369f;  // 1/sqrt(32)

    const int lcol = tid >> 2, lds = (tid & 3) * 8;

    for (int n0 = 0; n0 < 1024; n0 += 64) {
        // cooperative load: k flat, v transposed
        {
            const float4* ksrc = (const float4*)&kbase[(n0 + lcol) * 32 + lds];
            float4 k1 = ksrc[0], k2 = ksrc[1];
            *(float4*)&ks[lcol * 32 + lds]     = k1;
            *(float4*)&ks[lcol * 32 + lds + 4] = k2;
            const float4* vsrc = (const float4*)&vbase[(n0 + lcol) * 32 + lds];
            float4 v1 = vsrc[0], v2 = vsrc[1];
            vt[lds+0][lcol] = v1.x; vt[lds+1][lcol] = v1.y;
            vt[lds+2][lcol] = v1.z; vt[lds+3][lcol] = v1.w;
            vt[lds+4][lcol] = v2.x; vt[lds+5][lcol] = v2.y;
            vt[lds+6][lcol] = v2.z; vt[lds+7][lcol] = v2.w;
        }
        __syncthreads();

        // scores for this thread's 16 columns
        float s[16];
        #pragma unroll
        for (int j = 0; j < 16; j++) {
            const float* kc = &ks[(cg * 16 + j) * 32];
            float sa = 0.f;
            #pragma unroll
            for (int d = 0; d < 32; d += 4) {
                float4 k4 = *(const float4*)&kc[d];
                sa += q[d] * k4.x + q[d+1] * k4.y + q[d+2] * k4.z + q[d+3] * k4.w;
            }
            s[j] = sa * inv_sqrt_d;
        }
        // mask add
        #pragma unroll
        for (int j4 = 0; j4 < 16; j4 += 4) {
            float4 mk = *(const float4*)&mrow[n0 + cg * 16 + j4];
            s[j4]   += mk.x; s[j4+1] += mk.y; s[j4+2] += mk.z; s[j4+3] += mk.w;
        }
        // chunk max across this thread + 4-thread row group
        float mx = s[0];
        #pragma unroll
        for (int j = 1; j < 16; j++) mx = fmaxf(mx, s[j]);
        mx = fmaxf(mx, __shfl_xor_sync(0xffffffffu, mx, 1));
        mx = fmaxf(mx, __shfl_xor_sync(0xffffffffu, mx, 2));
        float mnew = fmaxf(mrun, mx);
        float corr = __expf(mrun - mnew);
        mrun = mnew;
        lrun *= corr;
        #pragma unroll
        for (int d = 0; d < 32; d++) acc[d] *= corr;
        #pragma unroll
        for (int j = 0; j < 16; j++) {
            s[j] = __expf(s[j] - mnew);
            lrun += s[j];
        }
        // PV accumulate: acc[d] += sum_j p_j * v[col_j][d]
        #pragma unroll
        for (int d = 0; d < 32; d++) {
            const float* vr = &vt[d][cg * 16];
            float a = acc[d];
            #pragma unroll
            for (int j = 0; j < 16; j++) a += s[j] * vr[j];
            acc[d] = a;
        }
        __syncthreads();
    }

    // reduce across the 4-thread row group
    #pragma unroll
    for (int d = 0; d < 32; d++) {
        acc[d] += __shfl_xor_sync(0xffffffffu, acc[d], 1);
        acc[d] += __shfl_xor_sync(0xffffffffu, acc[d], 2);
    }
    lrun += __shfl_xor_sync(0xffffffffu, lrun, 1);
    lrun += __shfl_xor_sync(0xffffffffu, lrun, 2);
    float inv = 1.f / lrun;

    // write out_concat [B,P,H*D]: thread cg writes d in [cg*8, cg*8+8)
    const int h = bh & 15;
    float* outp = &g_attn[((size_t)b * 256 + p) * 512 + h * 32];
    #pragma unroll
    for (int d = cg * 8; d < cg * 8 + 8; d += 4) {
        float4 o;
        o.x = acc[d] * inv; o.y = acc[d+1] * inv;
        o.z = acc[d+2] * inv; o.w = acc[d+3] * inv;
        *(float4*)&outp[d] = o;
    }
}

// ---------------------------------------------------------------------------
// Kernel C: mh = out_concat @ W_combine^T  (same shape as kernel A)
// ---------------------------------------------------------------------------
__global__ __launch_bounds__(256) void combine_kernel(const float* __restrict__ Wc)
{
    const int mtile = blockIdx.y * 64, otile = blockIdx.x * 64;
    __shared__ float As[16][64];
    __shared__ float Ws[16][64];
    const int tid = threadIdx.x, tx = tid & 15, ty = tid >> 4;
    const int lr = tid >> 2, lk = (tid & 3) * 4;
    float acc[4][4] = {};

    for (int k0 = 0; k0 < 512; k0 += 16) {
        float4 a = *(const float4*)&g_attn[(mtile + lr) * 512 + k0 + lk];
        As[lk+0][lr] = a.x; As[lk+1][lr] = a.y; As[lk+2][lr] = a.z; As[lk+3][lr] = a.w;
        float4 w = *(const float4*)&Wc[(otile + lr) * 512 + k0 + lk];
        Ws[lk+0][lr] = w.x; Ws[lk+1][lr] = w.y; Ws[lk+2][lr] = w.z; Ws[lk+3][lr] = w.w;
        __syncthreads();
        #pragma unroll
        for (int kk = 0; kk < 16; kk++) {
            float4 av = *(const float4*)&As[kk][ty * 4];
            float4 bv = *(const float4*)&Ws[kk][tx * 4];
            float aa[4] = {av.x, av.y, av.z, av.w};
            float bb[4] = {bv.x, bv.y, bv.z, bv.w};
            #pragma unroll
            for (int i = 0; i < 4; i++)
                #pragma unroll
                for (int j = 0; j < 4; j++)
                    acc[i][j] += aa[i] * bb[j];
        }
        __syncthreads();
    }
    #pragma unroll
    for (int i = 0; i < 4; i++) {
        int m = mtile + ty * 4 + i;
        float4 o;
        o.x = acc[i][0]; o.y = acc[i][1]; o.z = acc[i][2]; o.w = acc[i][3];
        *(float4*)&g_mh[m * 512 + otile + tx * 4] = o;
    }
}

// ---------------------------------------------------------------------------
// Kernel D: pointer scores + clipped-tanh softmax numerator
// score2 = mh @ shk / sqrt(E); out = exp(10*tanh(score2) + mask); rowsum atomics
// (tanh bounds logits to [-10,10] -> no max subtraction needed)
// ---------------------------------------------------------------------------
__global__ __launch_bounds__(256) void pointer_kernel(
    const float* __restrict__ shk, const float* __restrict__ mask,
    float* __restrict__ out)
{
    const int b = blockIdx.z;
    const int p0 = blockIdx.y * 64;
    const int n0 = blockIdx.x * 64;
    __shared__ float As[16][64];
    __shared__ float Bs[16][64];
    __shared__ float red[64][17];
    const int tid = threadIdx.x, tx = tid & 15, ty = tid >> 4;
    const int lr = tid >> 2, lk = (tid & 3) * 4;   // A loader
    const int br = tid >> 4, bc = (tid & 15) * 4;  // B loader
    float acc[4][4] = {};

    const float* Ab = g_mh + ((size_t)b * 256 + p0) * 512;
    const float* Bb = shk + (size_t)b * 512 * 1024 + n0;

    for (int k0 = 0; k0 < 512; k0 += 16) {
        float4 a = *(const float4*)&Ab[lr * 512 + k0 + lk];
        As[lk+0][lr] = a.x; As[lk+1][lr] = a.y; As[lk+2][lr] = a.z; As[lk+3][lr] = a.w;
        float4 bvv = *(const float4*)&Bb[(size_t)(k0 + br) * 1024 + bc];
        *(float4*)&Bs[br][bc] = bvv;
        __syncthreads();
        #pragma unroll
        for (int kk = 0; kk < 16; kk++) {
            float4 av = *(const float4*)&As[kk][ty * 4];
            float4 bv = *(const float4*)&Bs[kk][tx * 4];
            float aa[4] = {av.x, av.y, av.z, av.w};
            float bb[4] = {bv.x, bv.y, bv.z, bv.w};
            #pragma unroll
            for (int i = 0; i < 4; i++)
                #pragma unroll
                for (int j = 0; j < 4; j++)
                    acc[i][j] += aa[i] * bb[j];
        }
        __syncthreads();
    }

    const float invE = 0.04419417382415922f;  // 1/sqrt(512)
    #pragma unroll
    for (int i = 0; i < 4; i++) {
        int p = p0 + ty * 4 + i;
        int n = n0 + tx * 4;
        size_t oidx = ((size_t)b * 256 + p) * 1024 + n;
        float4 mk = *(const float4*)&mask[oidx];
        float mkv[4] = {mk.x, mk.y, mk.z, mk.w};
        float rs = 0.f;
        float vals[4];
        #pragma unroll
        for (int j = 0; j < 4; j++) {
            float t = 10.f * tanhf(acc[i][j] * invE);
            float e = __expf(t + mkv[j]);   // masked: exp(-1e9) == 0
            vals[j] = e; rs += e;
        }
        float4 o; o.x = vals[0]; o.y = vals[1]; o.z = vals[2]; o.w = vals[3];
        *(float4*)&out[oidx] = o;
        red[ty * 4 + i][tx] = rs;
    }
    __syncthreads();
    if (tid < 64) {
        float s = 0.f;
        #pragma unroll
        for (int t = 0; t < 16; t++) s += red[tid][t];
        atomicAdd(&g_rowsum[b * 256 + p0 + tid], s);
    }
}

// ---------------------------------------------------------------------------
// helpers: zero rowsums, final normalize
// ---------------------------------------------------------------------------
__global__ void zero_rowsum_kernel()
{
    int i = blockIdx.x * blockDim.x + threadIdx.x;
    if (i < Bn * Pn) g_rowsum[i] = 0.f;
}

__global__ void normalize_kernel(float* __restrict__ out)
{
    int i = blockIdx.x * blockDim.x + threadIdx.x;  // float4 index
    size_t i4 = (size_t)i * 4;
    int row = (int)(i4 >> 10);  // N=1024 per row, 4 | 1024
    float inv = 1.f / g_rowsum[row];
    float4 v = *(float4*)&out[i4];
    v.x *= inv; v.y *= inv; v.z *= inv; v.w *= inv;
    *(float4*)&out[i4] = v;
}

// ---------------------------------------------------------------------------
extern "C" void kernel_launch(void* const* d_in, const int* in_sizes, int n_in,
                              void* d_out, int out_size)
{
    const float* enc  = (const float*)d_in[0];  // encoded_last_node [B,P,E]
    const float* mask = (const float*)d_in[1];  // ninf_mask [B,P,N]
    const float* qf   = (const float*)d_in[2];  // q_first [B,H,P,D]
    const float* kmat = (const float*)d_in[3];  // k [B,H,N,D]
    const float* vmat = (const float*)d_in[4];  // v [B,H,N,D]
    const float* shk  = (const float*)d_in[5];  // single_head_key [B,E,N]
    const float* Wq   = (const float*)d_in[6];  // Wq_last [E,H*D]
    const float* Wc   = (const float*)d_in[7];  // W_combine [H*D,E]
    float* out = (float*)d_out;                 // probs [B,P,N]

    zero_rowsum_kernel<<<32, 256>>>();
    qlast_kernel<<<dim3(8, 128), 256>>>(enc, Wq, qf);
    attn_kernel<<<dim3(512, 4), 256>>>(kmat, vmat, mask);
    combine_kernel<<<dim3(8, 128), 256>>>(Wc);
    pointer_kernel<<<dim3(16, 4, 32), 256>>>(shk, mask, out);
    normalize_kernel<<<8192, 256>>>(out);
}